// round 1
// baseline (speedup 1.0000x reference)
#include <cuda_runtime.h>
#include <math.h>
#include <math_constants.h>

// ---------------- problem constants (fixed by the dataset) ----------------
#define NN    50000
#define EE    800000
#define ENT   (EE + NN)          // edges incl. self loops = 850000
#define IND   512
#define HID   128
#define HEADS 4
#define D1    (HEADS * HID)      // 512
#define OUTD  64
#define NC    4

// ---------------- scratch (static device memory; no allocs) ----------------
__device__ __align__(16) float g_h1pre[(size_t)NN * D1];   // x@W1           102.4 MB
__device__ __align__(16) float g_out1 [(size_t)NN * D1];   // GAT1 agg / h1  102.4 MB
__device__ __align__(16) float g_h2pre[(size_t)NN * OUTD]; // h1@W2           12.8 MB
__device__ __align__(16) float g_out2 [(size_t)NN * OUTD]; // GAT2 agg / h2   12.8 MB
__device__ float g_as1[NN * HEADS], g_ad1[NN * HEADS];
__device__ float g_m1 [NN * HEADS], g_s1 [NN * HEADS];
__device__ float g_as2[NN], g_ad2[NN], g_m2[NN], g_s2[NN];
__device__ float g_scores[NN];
__device__ float g_red2[2];              // global softmax {max, sum}
__device__ float g_cn[NC * OUTD];        // normalized class_attn

// ---------------- helpers ----------------
__device__ __forceinline__ float lrelu(float v) { return v > 0.f ? v : 0.2f * v; }

__device__ __forceinline__ void atomicMaxF(float* addr, float val) {
    int* ia = (int*)addr;
    int old = *ia;
    while (__int_as_float(old) < val) {
        int assumed = old;
        old = atomicCAS(ia, assumed, __float_as_int(val));
        if (old == assumed) break;
    }
}

__device__ __forceinline__ void redAddV4(float* p, float a, float b, float c, float d) {
    asm volatile("red.global.add.v4.f32 [%0], {%1,%2,%3,%4};"
                 :: "l"(p), "f"(a), "f"(b), "f"(c), "f"(d) : "memory");
}

// ---------------- init: zero accumulators, -inf maxes ----------------
__global__ void init_kernel() {
    const size_t tid = (size_t)blockIdx.x * blockDim.x + threadIdx.x;
    const size_t stride = (size_t)gridDim.x * blockDim.x;
    for (size_t i = tid; i < (size_t)NN * D1; i += stride) g_out1[i] = 0.f;
    for (size_t i = tid; i < (size_t)NN * OUTD; i += stride) g_out2[i] = 0.f;
    for (size_t i = tid; i < (size_t)NN * HEADS; i += stride) { g_m1[i] = -CUDART_INF_F; g_s1[i] = 0.f; }
    for (size_t i = tid; i < (size_t)NN; i += stride) { g_m2[i] = -CUDART_INF_F; g_s2[i] = 0.f; }
}

// ---------------- generic register-blocked fp32 SGEMM: C = A@B ----------------
template<int BM, int BN, int BK, int TM, int TN>
__global__ void sgemm_kernel(int M, int N, int K,
                             const float* __restrict__ A,
                             const float* __restrict__ B,
                             float* __restrict__ C) {
    __shared__ float As[BK][BM];
    __shared__ float Bs[BK][BN];
    constexpr int NT = (BM / TM) * (BN / TN);
    const int tid = threadIdx.x;
    const int tx = tid % (BN / TN);
    const int ty = tid / (BN / TN);
    const int rowBase = blockIdx.y * BM;
    const int colBase = blockIdx.x * BN;

    float acc[TM][TN];
#pragma unroll
    for (int i = 0; i < TM; i++)
#pragma unroll
        for (int j = 0; j < TN; j++) acc[i][j] = 0.f;

    for (int k0 = 0; k0 < K; k0 += BK) {
        for (int idx = tid; idx < BM * BK; idx += NT) {
            int r = idx / BK, c = idx % BK;
            int gr = rowBase + r;
            As[c][r] = (gr < M) ? A[(size_t)gr * K + k0 + c] : 0.f;
        }
        for (int idx = tid; idx < BK * BN; idx += NT) {
            int r = idx / BN, c = idx % BN;
            Bs[r][c] = B[(size_t)(k0 + r) * N + colBase + c];
        }
        __syncthreads();
#pragma unroll
        for (int k = 0; k < BK; k++) {
            float ra[TM], rb[TN];
#pragma unroll
            for (int i = 0; i < TM; i++) ra[i] = As[k][ty * TM + i];
#pragma unroll
            for (int j = 0; j < TN; j++) rb[j] = Bs[k][tx * TN + j];
#pragma unroll
            for (int i = 0; i < TM; i++)
#pragma unroll
                for (int j = 0; j < TN; j++) acc[i][j] += ra[i] * rb[j];
        }
        __syncthreads();
    }
#pragma unroll
    for (int i = 0; i < TM; i++) {
        int gr = rowBase + ty * TM + i;
        if (gr >= M) continue;
#pragma unroll
        for (int j = 0; j < TN; j++)
            C[(size_t)gr * N + colBase + tx * TN + j] = acc[i][j];
    }
}

// ---------------- GAT layer 1: attention scalars per node/head ----------------
__global__ void scores1_kernel(const float* __restrict__ att_src1,
                               const float* __restrict__ att_dst1) {
    const int n = blockIdx.x;
    const int h = threadIdx.x >> 5;
    const int lane = threadIdx.x & 31;
    const float* hr = g_h1pre + (size_t)n * D1 + h * HID;
    const float* as = att_src1 + h * HID;
    const float* ad = att_dst1 + h * HID;
    float sa = 0.f, sd = 0.f;
    for (int i = lane; i < HID; i += 32) {
        float v = hr[i];
        sa += v * as[i];
        sd += v * ad[i];
    }
#pragma unroll
    for (int o = 16; o > 0; o >>= 1) {
        sa += __shfl_xor_sync(0xffffffffu, sa, o);
        sd += __shfl_xor_sync(0xffffffffu, sd, o);
    }
    if (lane == 0) { g_as1[n * HEADS + h] = sa; g_ad1[n * HEADS + h] = sd; }
}

__global__ void edge_max1_kernel(const int* __restrict__ ei) {
    int e = blockIdx.x * blockDim.x + threadIdx.x;
    if (e >= ENT) return;
    int s = (e < EE) ? ei[e] : (e - EE);
    int d = (e < EE) ? ei[EE + e] : (e - EE);
#pragma unroll
    for (int h = 0; h < HEADS; h++) {
        float ev = lrelu(g_as1[s * HEADS + h] + g_ad1[d * HEADS + h]);
        atomicMaxF(&g_m1[d * HEADS + h], ev);
    }
}

__global__ void edge_sum1_kernel(const int* __restrict__ ei) {
    int e = blockIdx.x * blockDim.x + threadIdx.x;
    if (e >= ENT) return;
    int s = (e < EE) ? ei[e] : (e - EE);
    int d = (e < EE) ? ei[EE + e] : (e - EE);
#pragma unroll
    for (int h = 0; h < HEADS; h++) {
        float ev = lrelu(g_as1[s * HEADS + h] + g_ad1[d * HEADS + h]);
        atomicAdd(&g_s1[d * HEADS + h], expf(ev - g_m1[d * HEADS + h]));
    }
}

// one block (128 threads) per edge: 512 floats = 128 float4
__global__ void edge_msg1_kernel(const int* __restrict__ ei) {
    const int e = blockIdx.x;
    const int t = threadIdx.x;
    const int s = (e < EE) ? ei[e] : (e - EE);
    const int d = (e < EE) ? ei[EE + e] : (e - EE);
    __shared__ float al[HEADS];
    if (t < HEADS) {
        float ev = lrelu(g_as1[s * HEADS + t] + g_ad1[d * HEADS + t]);
        float ex = expf(ev - g_m1[d * HEADS + t]);
        al[t] = ex / (g_s1[d * HEADS + t] + 1e-16f);
    }
    __syncthreads();
    const float a = al[t >> 5];                 // head = t/32 (128 feat/head = 32 float4)
    float4 v = *(const float4*)(g_h1pre + (size_t)s * D1 + t * 4);
    float* p = g_out1 + (size_t)d * D1 + t * 4;
    redAddV4(p, v.x * a, v.y * a, v.z * a, v.w * a);
}

__global__ void elu1_kernel(const float* __restrict__ b1) {
    size_t i = (size_t)blockIdx.x * blockDim.x + threadIdx.x;
    if (i >= (size_t)NN * D1) return;
    float v = g_out1[i] + b1[i & (D1 - 1)];
    g_out1[i] = v > 0.f ? v : expm1f(v);
}

// ---------------- GAT layer 2 ----------------
__global__ void scores2_kernel(const float* __restrict__ att_src2,
                               const float* __restrict__ att_dst2) {
    const int n = blockIdx.x;
    const int lane = threadIdx.x;
    const float* hr = g_h2pre + (size_t)n * OUTD;
    float sa = 0.f, sd = 0.f;
    for (int i = lane; i < OUTD; i += 32) {
        float v = hr[i];
        sa += v * att_src2[i];
        sd += v * att_dst2[i];
    }
#pragma unroll
    for (int o = 16; o > 0; o >>= 1) {
        sa += __shfl_xor_sync(0xffffffffu, sa, o);
        sd += __shfl_xor_sync(0xffffffffu, sd, o);
    }
    if (lane == 0) { g_as2[n] = sa; g_ad2[n] = sd; }
}

__global__ void edge_max2_kernel(const int* __restrict__ ei) {
    int e = blockIdx.x * blockDim.x + threadIdx.x;
    if (e >= ENT) return;
    int s = (e < EE) ? ei[e] : (e - EE);
    int d = (e < EE) ? ei[EE + e] : (e - EE);
    atomicMaxF(&g_m2[d], lrelu(g_as2[s] + g_ad2[d]));
}

__global__ void edge_sum2_kernel(const int* __restrict__ ei) {
    int e = blockIdx.x * blockDim.x + threadIdx.x;
    if (e >= ENT) return;
    int s = (e < EE) ? ei[e] : (e - EE);
    int d = (e < EE) ? ei[EE + e] : (e - EE);
    float ev = lrelu(g_as2[s] + g_ad2[d]);
    atomicAdd(&g_s2[d], expf(ev - g_m2[d]));
}

// 16 threads per edge: 64 floats = 16 float4
__global__ void edge_msg2_kernel(const int* __restrict__ ei) {
    int idx = blockIdx.x * blockDim.x + threadIdx.x;
    int e = idx >> 4;
    int q = idx & 15;
    if (e >= ENT) return;
    int s = (e < EE) ? ei[e] : (e - EE);
    int d = (e < EE) ? ei[EE + e] : (e - EE);
    float ev = lrelu(g_as2[s] + g_ad2[d]);
    float a = expf(ev - g_m2[d]) / (g_s2[d] + 1e-16f);
    float4 v = *(const float4*)(g_h2pre + (size_t)s * OUTD + q * 4);
    float* p = g_out2 + (size_t)d * OUTD + q * 4;
    redAddV4(p, v.x * a, v.y * a, v.z * a, v.w * a);
}

__global__ void bias2_kernel(const float* __restrict__ b2) {
    size_t i = (size_t)blockIdx.x * blockDim.x + threadIdx.x;
    if (i >= (size_t)NN * OUTD) return;
    g_out2[i] += b2[i & (OUTD - 1)];
}

// ---------------- intra-sample attention score per node ----------------
__global__ void attn_score_kernel(const float* __restrict__ Wa,
                                  const float* __restrict__ ba,
                                  const float* __restrict__ wv,
                                  const float* __restrict__ bv) {
    const int n = blockIdx.x;
    const int j = threadIdx.x;          // 64 threads
    __shared__ float hrow[OUTD];
    __shared__ float sh[OUTD];
    hrow[j] = g_out2[(size_t)n * OUTD + j];
    __syncthreads();
    float acc = 0.f;
#pragma unroll
    for (int k = 0; k < OUTD; k++) acc += hrow[k] * Wa[k * OUTD + j];
    float t = tanhf(acc + ba[j]);
    sh[j] = t * wv[j];
    __syncthreads();
    if (j < 32) sh[j] += sh[j + 32];
    __syncthreads();
    if (j == 0) {
        float s = 0.f;
        for (int k = 0; k < 32; k++) s += sh[k];
        g_scores[n] = s + bv[0];
    }
}

// ---------------- global softmax reduction + class_attn normalize ----------------
__global__ void global_reduce_kernel(const float* __restrict__ class_attn) {
    __shared__ float sm[1024];
    const int t = threadIdx.x;
    float m = -CUDART_INF_F;
    for (int i = t; i < NN; i += 1024) m = fmaxf(m, g_scores[i]);
    sm[t] = m; __syncthreads();
    for (int s = 512; s > 0; s >>= 1) { if (t < s) sm[t] = fmaxf(sm[t], sm[t + s]); __syncthreads(); }
    const float gmax = sm[0];
    __syncthreads();
    float ssum = 0.f;
    for (int i = t; i < NN; i += 1024) ssum += expf(g_scores[i] - gmax);
    sm[t] = ssum; __syncthreads();
    for (int s = 512; s > 0; s >>= 1) { if (t < s) sm[t] += sm[t + s]; __syncthreads(); }
    if (t == 0) { g_red2[0] = gmax; g_red2[1] = sm[0]; }

    if (t < NC * 32) {
        int c = t >> 5, lane = t & 31;
        float sq = 0.f;
        for (int jj = lane; jj < OUTD; jj += 32) { float v = class_attn[c * OUTD + jj]; sq += v * v; }
#pragma unroll
        for (int o = 16; o > 0; o >>= 1) sq += __shfl_xor_sync(0xffffffffu, sq, o);
        float nrm = fmaxf(sqrtf(sq), 1e-12f);
        for (int jj = lane; jj < OUTD; jj += 32) g_cn[c * OUTD + jj] = class_attn[c * OUTD + jj] / nrm;
    }
}

// ---------------- final epilogue: xw, out, inter_class_scores ----------------
__global__ void final_kernel(const float* __restrict__ Wc,
                             const float* __restrict__ bc,
                             float* __restrict__ out) {
    const int n = blockIdx.x;
    const int j = threadIdx.x;  // 64 threads
    __shared__ float sxw[OUTD];
    __shared__ float ssq[OUTD];
    const float attw = expf(g_scores[n] - g_red2[0]) / g_red2[1];
    const float xw = g_out2[(size_t)n * OUTD + j] * attw;
    sxw[j] = xw;
    ssq[j] = xw * xw;
    out[(size_t)NN * NC + (size_t)n * OUTD + j] = xw;   // xw section
    __syncthreads();
    if (j < 32) ssq[j] += ssq[j + 32];
    __syncthreads();
    if (j == 0) {
        float s = 0.f;
        for (int k = 0; k < 32; k++) s += ssq[k];
        ssq[0] = fmaxf(sqrtf(s), 1e-12f);
    }
    __syncthreads();
    const float inv = 1.f / ssq[0];
    if (j < NC) {
        float accI = 0.f, accO = bc[j];
#pragma unroll
        for (int k = 0; k < OUTD; k++) {
            accI += sxw[k] * inv * g_cn[j * OUTD + k];
            accO += sxw[k] * Wc[k * NC + j];
        }
        out[(size_t)n * NC + j] = accO;                                 // out section
        out[(size_t)NN * (NC + OUTD) + (size_t)n * NC + j] = accI;      // inter section
    }
}

// ---------------- launch ----------------
extern "C" void kernel_launch(void* const* d_in, const int* in_sizes, int n_in,
                              void* d_out, int out_size) {
    const float* x        = (const float*)d_in[0];
    const int*   ei       = (const int*)  d_in[1];
    const float* W1       = (const float*)d_in[2];
    const float* att_src1 = (const float*)d_in[3];
    const float* att_dst1 = (const float*)d_in[4];
    const float* b1       = (const float*)d_in[5];
    const float* W2       = (const float*)d_in[6];
    const float* att_src2 = (const float*)d_in[7];
    const float* att_dst2 = (const float*)d_in[8];
    const float* b2       = (const float*)d_in[9];
    const float* Wa       = (const float*)d_in[10];
    const float* ba       = (const float*)d_in[11];
    const float* wv       = (const float*)d_in[12];
    const float* bv       = (const float*)d_in[13];
    const float* class_attn = (const float*)d_in[14];
    const float* Wc       = (const float*)d_in[15];
    const float* bc       = (const float*)d_in[16];
    float* out = (float*)d_out;

    float *h1pre_p, *out1_p, *h2pre_p;
    cudaGetSymbolAddress((void**)&h1pre_p, g_h1pre);
    cudaGetSymbolAddress((void**)&out1_p,  g_out1);
    cudaGetSymbolAddress((void**)&h2pre_p, g_h2pre);

    init_kernel<<<2048, 256>>>();

    // GEMM1: h1pre = x @ W1   [50000,512] @ [512,512]
    {
        dim3 grid(D1 / 128, (NN + 127) / 128);
        sgemm_kernel<128, 128, 8, 8, 8><<<grid, 256>>>(NN, D1, IND, x, W1, h1pre_p);
    }
    scores1_kernel<<<NN, 128>>>(att_src1, att_dst1);

    const int eb = (ENT + 255) / 256;
    edge_max1_kernel<<<eb, 256>>>(ei);
    edge_sum1_kernel<<<eb, 256>>>(ei);
    edge_msg1_kernel<<<ENT, 128>>>(ei);
    elu1_kernel<<<(int)(((size_t)NN * D1 + 255) / 256), 256>>>(b1);

    // GEMM2: h2pre = h1 @ W2   [50000,512] @ [512,64]
    {
        dim3 grid(OUTD / 64, (NN + 127) / 128);
        sgemm_kernel<128, 64, 8, 8, 4><<<grid, 256>>>(NN, OUTD, D1, out1_p, W2, h2pre_p);
    }
    scores2_kernel<<<NN, 32>>>(att_src2, att_dst2);
    edge_max2_kernel<<<eb, 256>>>(ei);
    edge_sum2_kernel<<<eb, 256>>>(ei);
    edge_msg2_kernel<<<(ENT * 16 + 255) / 256, 256>>>(ei);
    bias2_kernel<<<(NN * OUTD + 255) / 256, 256>>>(b2);

    attn_score_kernel<<<NN, 64>>>(Wa, ba, wv, bv);
    global_reduce_kernel<<<1, 1024>>>(class_attn);
    final_kernel<<<NN, 64>>>(Wc, bc, out);
}

// round 2
// speedup vs baseline: 1.5297x; 1.5297x over previous
#include <cuda_runtime.h>
#include <math.h>
#include <math_constants.h>

// ---------------- problem constants ----------------
#define NN    50000
#define EE    800000
#define ENT   (EE + NN)          // edges incl. self loops
#define IND   512
#define HID   128
#define HEADS 4
#define D1    (HEADS * HID)      // 512
#define OUTD  64
#define NC    4

// ---------------- scratch (static device memory) ----------------
__device__ __align__(16) float g_h1pre[(size_t)NN * D1];
__device__ __align__(16) float g_out1 [(size_t)NN * D1];
__device__ __align__(16) float g_h2pre[(size_t)NN * OUTD];
__device__ __align__(16) float g_out2 [(size_t)NN * OUTD];
__device__ float g_as1[NN * HEADS], g_ad1[NN * HEADS], g_s1[NN * HEADS];
__device__ float g_as2[NN], g_ad2[NN], g_s2[NN];
__device__ float g_scores[NN];
__device__ float g_red2[2];
__device__ float g_cn[NC * OUTD];

__device__ __forceinline__ float lrelu(float v) { return v > 0.f ? v : 0.2f * v; }

__device__ __forceinline__ void redAddV4(float* p, float a, float b, float c, float d) {
    asm volatile("red.global.add.v4.f32 [%0], {%1,%2,%3,%4};"
                 :: "l"(p), "f"(a), "f"(b), "f"(c), "f"(d) : "memory");
}

// ---------------- init: zero only the true accumulators ----------------
__global__ void init_kernel() {
    const size_t tid = (size_t)blockIdx.x * blockDim.x + threadIdx.x;
    const size_t stride = (size_t)gridDim.x * blockDim.x;
    float4 z = make_float4(0.f, 0.f, 0.f, 0.f);
    float4* o1 = (float4*)g_out1;
    float4* o2 = (float4*)g_out2;
    for (size_t i = tid; i < (size_t)NN * D1 / 4; i += stride) o1[i] = z;
    for (size_t i = tid; i < (size_t)NN * OUTD / 4; i += stride) o2[i] = z;
    for (size_t i = tid; i < (size_t)NN * HEADS; i += stride) g_s1[i] = 0.f;
    for (size_t i = tid; i < (size_t)NN; i += stride) g_s2[i] = 0.f;
}

// ---------------- double-buffered vectorized SGEMM: C[M,N] = A[M,K]@B[K,N] ----------------
template<int BM, int BN, int BK, int TM, int TN, int K, int N>
__global__ __launch_bounds__((BM / TM) * (BN / TN))
void sgemm_kernel(int M, const float* __restrict__ A,
                  const float* __restrict__ B, float* __restrict__ C) {
    constexpr int NT = (BM / TM) * (BN / TN);
    __shared__ float As[2][BK][BM];
    __shared__ float Bs[2][BK][BN];

    const int tid = threadIdx.x;
    const int tx = tid % (BN / TN);
    const int ty = tid / (BN / TN);
    const int rowBase = blockIdx.y * BM;
    const int colBase = blockIdx.x * BN;

    // A-load mapping: float4 along K
    constexpr int A_K4 = BK / 4;
    constexpr int A_RS = NT / A_K4;              // row stride per pass
    constexpr int A_IT = BM / A_RS;
    const int a_row = tid / A_K4;
    const int a_col = (tid % A_K4) * 4;
    // B-load mapping: float4 along N
    constexpr int B_N4 = BN / 4;
    constexpr int B_RS = NT / B_N4;
    constexpr int B_IT = BK / B_RS;
    const int b_row = tid / B_N4;
    const int b_col = (tid % B_N4) * 4;

    float4 aReg[A_IT], bReg[B_IT];

    auto loadG = [&](int k0) {
#pragma unroll
        for (int i = 0; i < A_IT; i++) {
            int gr = rowBase + a_row + i * A_RS;
            aReg[i] = (gr < M) ? *(const float4*)(A + (size_t)gr * K + k0 + a_col)
                               : make_float4(0.f, 0.f, 0.f, 0.f);
        }
#pragma unroll
        for (int i = 0; i < B_IT; i++)
            bReg[i] = *(const float4*)(B + (size_t)(k0 + b_row + i * B_RS) * N + colBase + b_col);
    };
    auto storeS = [&](int buf) {
#pragma unroll
        for (int i = 0; i < A_IT; i++) {
            int r = a_row + i * A_RS;
            As[buf][a_col + 0][r] = aReg[i].x;
            As[buf][a_col + 1][r] = aReg[i].y;
            As[buf][a_col + 2][r] = aReg[i].z;
            As[buf][a_col + 3][r] = aReg[i].w;
        }
#pragma unroll
        for (int i = 0; i < B_IT; i++)
            *(float4*)&Bs[buf][b_row + i * B_RS][b_col] = bReg[i];
    };

    float acc[TM][TN];
#pragma unroll
    for (int i = 0; i < TM; i++)
#pragma unroll
        for (int j = 0; j < TN; j++) acc[i][j] = 0.f;

    auto compute = [&](int buf) {
#pragma unroll
        for (int k = 0; k < BK; k++) {
            float ra[TM], rb[TN];
#pragma unroll
            for (int i = 0; i < TM; i++) ra[i] = As[buf][k][ty * TM + i];
#pragma unroll
            for (int j = 0; j < TN; j++) rb[j] = Bs[buf][k][tx * TN + j];
#pragma unroll
            for (int i = 0; i < TM; i++)
#pragma unroll
                for (int j = 0; j < TN; j++) acc[i][j] = fmaf(ra[i], rb[j], acc[i][j]);
        }
    };

    loadG(0);
    storeS(0);
    __syncthreads();
    int buf = 0;
    for (int k0 = BK; k0 < K; k0 += BK) {
        loadG(k0);
        compute(buf);
        storeS(buf ^ 1);
        __syncthreads();
        buf ^= 1;
    }
    compute(buf);

#pragma unroll
    for (int i = 0; i < TM; i++) {
        int gr = rowBase + ty * TM + i;
        if (gr >= M) continue;
#pragma unroll
        for (int j = 0; j < TN; j += 4) {
            float4 v = make_float4(acc[i][j], acc[i][j + 1], acc[i][j + 2], acc[i][j + 3]);
            *(float4*)(C + (size_t)gr * N + colBase + tx * TN + j) = v;
        }
    }
}

// ---------------- GAT1: per-node/head attention scalars ----------------
__global__ void scores1_kernel(const float* __restrict__ att_src1,
                               const float* __restrict__ att_dst1) {
    const int n = blockIdx.x;
    const int h = threadIdx.x >> 5;
    const int lane = threadIdx.x & 31;
    const float* hr = g_h1pre + (size_t)n * D1 + h * HID;
    float sa = 0.f, sd = 0.f;
    for (int i = lane; i < HID; i += 32) {
        float v = hr[i];
        sa += v * att_src1[h * HID + i];
        sd += v * att_dst1[h * HID + i];
    }
#pragma unroll
    for (int o = 16; o > 0; o >>= 1) {
        sa += __shfl_xor_sync(0xffffffffu, sa, o);
        sd += __shfl_xor_sync(0xffffffffu, sd, o);
    }
    if (lane == 0) { g_as1[n * HEADS + h] = sa; g_ad1[n * HEADS + h] = sd; }
}

// ---------------- GAT1: single fused edge pass (exp-weight scatter + denom) ----------------
// one block (128 threads) per edge; warp w handles head w (32 float4 = 128 feats)
__global__ void edge_msg1_kernel(const int* __restrict__ ei) {
    const int e = blockIdx.x;
    const int t = threadIdx.x;
    const int w = t >> 5, lane = t & 31;
    const int s = (e < EE) ? __ldg(ei + e) : (e - EE);
    const int d = (e < EE) ? __ldg(ei + EE + e) : (e - EE);
    float a = 0.f;
    if (lane == 0) {
        float ev = lrelu(g_as1[s * HEADS + w] + g_ad1[d * HEADS + w]);
        a = expf(ev);
        atomicAdd(&g_s1[d * HEADS + w], a);   // softmax denominator, deferred division
    }
    a = __shfl_sync(0xffffffffu, a, 0);
    float4 v = *(const float4*)(g_h1pre + (size_t)s * D1 + t * 4);
    redAddV4(g_out1 + (size_t)d * D1 + t * 4, v.x * a, v.y * a, v.z * a, v.w * a);
}

// ---------------- GAT1 epilogue: divide by denom, +bias, ELU (float4) ----------------
__global__ void elu1_kernel(const float* __restrict__ b1) {
    size_t i4 = (size_t)blockIdx.x * blockDim.x + threadIdx.x;
    if (i4 >= (size_t)NN * (D1 / 4)) return;
    int row = (int)(i4 >> 7);
    int c4 = (int)(i4 & 127);
    int h = c4 >> 5;
    float inv = 1.f / (g_s1[row * HEADS + h] + 1e-16f);
    float4 v = ((float4*)g_out1)[i4];
    float4 b = ((const float4*)b1)[c4];
    v.x = v.x * inv + b.x; v.y = v.y * inv + b.y;
    v.z = v.z * inv + b.z; v.w = v.w * inv + b.w;
    v.x = v.x > 0.f ? v.x : expm1f(v.x);
    v.y = v.y > 0.f ? v.y : expm1f(v.y);
    v.z = v.z > 0.f ? v.z : expm1f(v.z);
    v.w = v.w > 0.f ? v.w : expm1f(v.w);
    ((float4*)g_out1)[i4] = v;
}

// ---------------- GAT2 scalars ----------------
__global__ void scores2_kernel(const float* __restrict__ att_src2,
                               const float* __restrict__ att_dst2) {
    const int n = blockIdx.x;
    const int lane = threadIdx.x;
    const float* hr = g_h2pre + (size_t)n * OUTD;
    float sa = 0.f, sd = 0.f;
    for (int i = lane; i < OUTD; i += 32) {
        float v = hr[i];
        sa += v * att_src2[i];
        sd += v * att_dst2[i];
    }
#pragma unroll
    for (int o = 16; o > 0; o >>= 1) {
        sa += __shfl_xor_sync(0xffffffffu, sa, o);
        sd += __shfl_xor_sync(0xffffffffu, sd, o);
    }
    if (lane == 0) { g_as2[n] = sa; g_ad2[n] = sd; }
}

// ---------------- GAT2: fused edge pass, 16 threads/edge ----------------
__global__ void edge_msg2_kernel(const int* __restrict__ ei) {
    int idx = blockIdx.x * blockDim.x + threadIdx.x;
    int e = idx >> 4;
    int q = idx & 15;
    if (e >= ENT) return;
    int s = (e < EE) ? __ldg(ei + e) : (e - EE);
    int d = (e < EE) ? __ldg(ei + EE + e) : (e - EE);
    float a = expf(lrelu(g_as2[s] + g_ad2[d]));
    if (q == 0) atomicAdd(&g_s2[d], a);
    float4 v = *(const float4*)(g_h2pre + (size_t)s * OUTD + q * 4);
    redAddV4(g_out2 + (size_t)d * OUTD + q * 4, v.x * a, v.y * a, v.z * a, v.w * a);
}

// ---------------- intra-attention: normalize + bias + MLP score (fused) ----------------
__global__ void attn_score_kernel(const float* __restrict__ b2,
                                  const float* __restrict__ Wa,
                                  const float* __restrict__ ba,
                                  const float* __restrict__ wv,
                                  const float* __restrict__ bv) {
    const int n = blockIdx.x;
    const int j = threadIdx.x;          // 64 threads
    __shared__ float hrow[OUTD];
    __shared__ float sh[OUTD];
    float inv = 1.f / (g_s2[n] + 1e-16f);
    float v = g_out1 == nullptr ? 0.f : 0.f; // (no-op, keeps compiler honest)
    v = g_out2[(size_t)n * OUTD + j] * inv + b2[j];
    g_out2[(size_t)n * OUTD + j] = v;   // write back normalized+biased h2
    hrow[j] = v;
    __syncthreads();
    float acc = 0.f;
#pragma unroll
    for (int k = 0; k < OUTD; k++) acc += hrow[k] * Wa[k * OUTD + j];
    sh[j] = tanhf(acc + ba[j]) * wv[j];
    __syncthreads();
    if (j < 32) sh[j] += sh[j + 32];
    __syncthreads();
    if (j == 0) {
        float s = 0.f;
#pragma unroll
        for (int k = 0; k < 32; k++) s += sh[k];
        g_scores[n] = s + bv[0];
    }
}

// ---------------- global softmax reduction + class_attn normalize ----------------
__global__ void global_reduce_kernel(const float* __restrict__ class_attn) {
    __shared__ float sm[1024];
    const int t = threadIdx.x;
    float m = -CUDART_INF_F;
    for (int i = t; i < NN; i += 1024) m = fmaxf(m, g_scores[i]);
    sm[t] = m; __syncthreads();
    for (int s = 512; s > 0; s >>= 1) { if (t < s) sm[t] = fmaxf(sm[t], sm[t + s]); __syncthreads(); }
    const float gmax = sm[0];
    __syncthreads();
    float ssum = 0.f;
    for (int i = t; i < NN; i += 1024) ssum += expf(g_scores[i] - gmax);
    sm[t] = ssum; __syncthreads();
    for (int s = 512; s > 0; s >>= 1) { if (t < s) sm[t] += sm[t + s]; __syncthreads(); }
    if (t == 0) { g_red2[0] = gmax; g_red2[1] = sm[0]; }

    if (t < NC * 32) {
        int c = t >> 5, lane = t & 31;
        float sq = 0.f;
        for (int jj = lane; jj < OUTD; jj += 32) { float v = class_attn[c * OUTD + jj]; sq += v * v; }
#pragma unroll
        for (int o = 16; o > 0; o >>= 1) sq += __shfl_xor_sync(0xffffffffu, sq, o);
        float nrm = fmaxf(sqrtf(sq), 1e-12f);
        for (int jj = lane; jj < OUTD; jj += 32) g_cn[c * OUTD + jj] = class_attn[c * OUTD + jj] / nrm;
    }
}

// ---------------- final epilogue ----------------
__global__ void final_kernel(const float* __restrict__ Wc,
                             const float* __restrict__ bc,
                             float* __restrict__ out) {
    const int n = blockIdx.x;
    const int j = threadIdx.x;  // 64 threads
    __shared__ float sxw[OUTD];
    __shared__ float ssq[OUTD];
    const float attw = expf(g_scores[n] - g_red2[0]) / g_red2[1];
    const float xw = g_out2[(size_t)n * OUTD + j] * attw;
    sxw[j] = xw;
    ssq[j] = xw * xw;
    out[(size_t)NN * NC + (size_t)n * OUTD + j] = xw;
    __syncthreads();
    if (j < 32) ssq[j] += ssq[j + 32];
    __syncthreads();
    if (j == 0) {
        float s = 0.f;
#pragma unroll
        for (int k = 0; k < 32; k++) s += ssq[k];
        ssq[0] = fmaxf(sqrtf(s), 1e-12f);
    }
    __syncthreads();
    const float inv = 1.f / ssq[0];
    if (j < NC) {
        float accI = 0.f, accO = bc[j];
#pragma unroll
        for (int k = 0; k < OUTD; k++) {
            accI += sxw[k] * inv * g_cn[j * OUTD + k];
            accO += sxw[k] * Wc[k * NC + j];
        }
        out[(size_t)n * NC + j] = accO;
        out[(size_t)NN * (NC + OUTD) + (size_t)n * NC + j] = accI;
    }
}

// ---------------- launch ----------------
extern "C" void kernel_launch(void* const* d_in, const int* in_sizes, int n_in,
                              void* d_out, int out_size) {
    const float* x        = (const float*)d_in[0];
    const int*   ei       = (const int*)  d_in[1];
    const float* W1       = (const float*)d_in[2];
    const float* att_src1 = (const float*)d_in[3];
    const float* att_dst1 = (const float*)d_in[4];
    const float* b1       = (const float*)d_in[5];
    const float* W2       = (const float*)d_in[6];
    const float* att_src2 = (const float*)d_in[7];
    const float* att_dst2 = (const float*)d_in[8];
    const float* b2       = (const float*)d_in[9];
    const float* Wa       = (const float*)d_in[10];
    const float* ba       = (const float*)d_in[11];
    const float* wv       = (const float*)d_in[12];
    const float* bv       = (const float*)d_in[13];
    const float* class_attn = (const float*)d_in[14];
    const float* Wc       = (const float*)d_in[15];
    const float* bc       = (const float*)d_in[16];
    float* out = (float*)d_out;

    float *h1pre_p, *out1_p, *h2pre_p;
    cudaGetSymbolAddress((void**)&h1pre_p, g_h1pre);
    cudaGetSymbolAddress((void**)&out1_p,  g_out1);
    cudaGetSymbolAddress((void**)&h2pre_p, g_h2pre);

    init_kernel<<<2048, 256>>>();

    // GEMM1: [50000,512] @ [512,512]
    {
        dim3 grid(D1 / 128, (NN + 127) / 128);
        sgemm_kernel<128, 128, 16, 8, 8, IND, D1><<<grid, 256>>>(NN, x, W1, h1pre_p);
    }
    scores1_kernel<<<NN, 128>>>(att_src1, att_dst1);
    edge_msg1_kernel<<<ENT, 128>>>(ei);
    elu1_kernel<<<(int)(((size_t)NN * (D1 / 4) + 255) / 256), 256>>>(b1);

    // GEMM2: [50000,512] @ [512,64]
    {
        dim3 grid(OUTD / 64, (NN + 127) / 128);
        sgemm_kernel<128, 64, 16, 8, 4, D1, OUTD><<<grid, 256>>>(NN, out1_p, W2, h2pre_p);
    }
    scores2_kernel<<<NN, 32>>>(att_src2, att_dst2);
    edge_msg2_kernel<<<(ENT * 16 + 255) / 256, 256>>>(ei);

    attn_score_kernel<<<NN, 64>>>(b2, Wa, ba, wv, bv);
    global_reduce_kernel<<<1, 1024>>>(class_attn);
    final_kernel<<<NN, 64>>>(Wc, bc, out);
}

// round 5
// speedup vs baseline: 2.0823x; 1.3613x over previous
#include <cuda_runtime.h>
#include <math.h>
#include <math_constants.h>

// ---------------- problem constants ----------------
#define NN    50000
#define EE    800000
#define ENT   (EE + NN)          // edges incl. self loops
#define IND   512
#define HID   128
#define HEADS 4
#define D1    (HEADS * HID)      // 512
#define OUTD  64
#define NC    4

// ---------------- scratch (static device memory) ----------------
__device__ __align__(16) float g_h1pre[(size_t)NN * D1];
__device__ __align__(16) float g_out1 [(size_t)NN * D1];   // h1 (post act)
__device__ __align__(16) float g_h2pre[(size_t)NN * OUTD];
__device__ __align__(16) float g_out2 [(size_t)NN * OUTD]; // h2 (final)
__device__ float g_as1[NN * HEADS], g_ad1[NN * HEADS];
__device__ float g_as2[NN], g_ad2[NN];
__device__ float g_scores[NN];
__device__ float g_red2[2];
__device__ float g_cn[NC * OUTD];
// CSR by destination
__device__ int g_deg[NN];
__device__ int g_off[NN + 1];
__device__ int g_cur[NN];
__device__ int g_csrc[ENT];

__device__ __forceinline__ float lrelu(float v) { return v > 0.f ? v : 0.2f * v; }

// ---------------- CSR build ----------------
__global__ void zero_deg_kernel() {
    int i = blockIdx.x * blockDim.x + threadIdx.x;
    if (i < NN) g_deg[i] = 0;
}

__global__ void hist_kernel(const int* __restrict__ ei) {
    for (int e = blockIdx.x * blockDim.x + threadIdx.x; e < ENT;
         e += gridDim.x * blockDim.x) {
        int d = (e < EE) ? __ldg(ei + EE + e) : (e - EE);
        atomicAdd(&g_deg[d], 1);
    }
}

// single block, 1024 threads: exclusive scan over 50000 degree bins
__global__ void scan_kernel() {
    __shared__ int sums[1024];
    const int t = threadIdx.x;
    const int per = (NN + 1023) / 1024;
    const int base = t * per;
    int lsum = 0;
    for (int i = 0; i < per; i++) {
        int idx = base + i;
        if (idx < NN) lsum += g_deg[idx];
    }
    sums[t] = lsum;
    __syncthreads();
    for (int o = 1; o < 1024; o <<= 1) {
        int y = (t >= o) ? sums[t - o] : 0;
        __syncthreads();
        sums[t] += y;
        __syncthreads();
    }
    int running = (t > 0) ? sums[t - 1] : 0;
    for (int i = 0; i < per; i++) {
        int idx = base + i;
        if (idx < NN) {
            g_off[idx] = running;
            g_cur[idx] = running;
            running += g_deg[idx];
        }
    }
    if (t == 0) g_off[NN] = ENT;
}

__global__ void scatter_kernel(const int* __restrict__ ei) {
    for (int e = blockIdx.x * blockDim.x + threadIdx.x; e < ENT;
         e += gridDim.x * blockDim.x) {
        int s = (e < EE) ? __ldg(ei + e) : (e - EE);
        int d = (e < EE) ? __ldg(ei + EE + e) : (e - EE);
        int pos = atomicAdd(&g_cur[d], 1);
        g_csrc[pos] = s;
    }
}

// ---------------- double-buffered vectorized SGEMM: C[M,N] = A[M,K]@B[K,N] ----------------
template<int BM, int BN, int BK, int TM, int TN, int K, int N>
__global__ __launch_bounds__((BM / TM) * (BN / TN))
void sgemm_kernel(int M, const float* __restrict__ A,
                  const float* __restrict__ B, float* __restrict__ C) {
    constexpr int NT = (BM / TM) * (BN / TN);
    __shared__ float As[2][BK][BM];
    __shared__ float Bs[2][BK][BN];

    const int tid = threadIdx.x;
    const int tx = tid % (BN / TN);
    const int ty = tid / (BN / TN);
    const int rowBase = blockIdx.y * BM;
    const int colBase = blockIdx.x * BN;

    constexpr int A_K4 = BK / 4;
    constexpr int A_RS = NT / A_K4;
    constexpr int A_IT = BM / A_RS;
    const int a_row = tid / A_K4;
    const int a_col = (tid % A_K4) * 4;
    constexpr int B_N4 = BN / 4;
    constexpr int B_RS = NT / B_N4;
    constexpr int B_IT = BK / B_RS;
    const int b_row = tid / B_N4;
    const int b_col = (tid % B_N4) * 4;

    float4 aReg[A_IT], bReg[B_IT];

    auto loadG = [&](int k0) {
#pragma unroll
        for (int i = 0; i < A_IT; i++) {
            int gr = rowBase + a_row + i * A_RS;
            aReg[i] = (gr < M) ? *(const float4*)(A + (size_t)gr * K + k0 + a_col)
                               : make_float4(0.f, 0.f, 0.f, 0.f);
        }
#pragma unroll
        for (int i = 0; i < B_IT; i++)
            bReg[i] = *(const float4*)(B + (size_t)(k0 + b_row + i * B_RS) * N + colBase + b_col);
    };
    auto storeS = [&](int buf) {
#pragma unroll
        for (int i = 0; i < A_IT; i++) {
            int r = a_row + i * A_RS;
            As[buf][a_col + 0][r] = aReg[i].x;
            As[buf][a_col + 1][r] = aReg[i].y;
            As[buf][a_col + 2][r] = aReg[i].z;
            As[buf][a_col + 3][r] = aReg[i].w;
        }
#pragma unroll
        for (int i = 0; i < B_IT; i++)
            *(float4*)&Bs[buf][b_row + i * B_RS][b_col] = bReg[i];
    };

    float acc[TM][TN];
#pragma unroll
    for (int i = 0; i < TM; i++)
#pragma unroll
        for (int j = 0; j < TN; j++) acc[i][j] = 0.f;

    auto compute = [&](int buf) {
#pragma unroll
        for (int k = 0; k < BK; k++) {
            float ra[TM], rb[TN];
#pragma unroll
            for (int i = 0; i < TM; i++) ra[i] = As[buf][k][ty * TM + i];
#pragma unroll
            for (int j = 0; j < TN; j++) rb[j] = Bs[buf][k][tx * TN + j];
#pragma unroll
            for (int i = 0; i < TM; i++)
#pragma unroll
                for (int j = 0; j < TN; j++) acc[i][j] = fmaf(ra[i], rb[j], acc[i][j]);
        }
    };

    loadG(0);
    storeS(0);
    __syncthreads();
    int buf = 0;
    for (int k0 = BK; k0 < K; k0 += BK) {
        loadG(k0);
        compute(buf);
        storeS(buf ^ 1);
        __syncthreads();
        buf ^= 1;
    }
    compute(buf);

#pragma unroll
    for (int i = 0; i < TM; i++) {
        int gr = rowBase + ty * TM + i;
        if (gr >= M) continue;
#pragma unroll
        for (int j = 0; j < TN; j += 4) {
            float4 v = make_float4(acc[i][j], acc[i][j + 1], acc[i][j + 2], acc[i][j + 3]);
            *(float4*)(C + (size_t)gr * N + colBase + tx * TN + j) = v;
        }
    }
}

// ---------------- GAT1: per-node/head attention scalars (float4 loads) ----------------
__global__ void scores1_kernel(const float* __restrict__ att_src1,
                               const float* __restrict__ att_dst1) {
    const int n = blockIdx.x;
    const int h = threadIdx.x >> 5;
    const int lane = threadIdx.x & 31;
    const float4* hr = (const float4*)(g_h1pre + (size_t)n * D1 + h * HID);
    const float4* as = (const float4*)(att_src1 + h * HID);
    const float4* ad = (const float4*)(att_dst1 + h * HID);
    float4 v = hr[lane];
    float4 a = as[lane];
    float4 d = ad[lane];
    float sa = v.x * a.x + v.y * a.y + v.z * a.z + v.w * a.w;
    float sd = v.x * d.x + v.y * d.y + v.z * d.z + v.w * d.w;
#pragma unroll
    for (int o = 16; o > 0; o >>= 1) {
        sa += __shfl_xor_sync(0xffffffffu, sa, o);
        sd += __shfl_xor_sync(0xffffffffu, sd, o);
    }
    if (lane == 0) { g_as1[n * HEADS + h] = sa; g_ad1[n * HEADS + h] = sd; }
}

// ---------------- GAT1 aggregation: one block (128 thr) per dst node ----------------
__global__ __launch_bounds__(128)
void agg1_kernel(const float* __restrict__ b1) {
    const int d = blockIdx.x;
    const int t = threadIdx.x;
    const int h = t >> 5;
    const int beg = __ldg(&g_off[d]);
    const int end = __ldg(&g_off[d + 1]);
    const float ad = g_ad1[d * HEADS + h];

    float4 acc = make_float4(0.f, 0.f, 0.f, 0.f);
    float den = 0.f;
    for (int i = beg; i < end; i++) {
        const int s = __ldg(&g_csrc[i]);
        const float a = expf(lrelu(__ldg(&g_as1[s * HEADS + h]) + ad));
        den += a;
        float4 v = *(const float4*)(g_h1pre + (size_t)s * D1 + t * 4);
        acc.x = fmaf(a, v.x, acc.x);
        acc.y = fmaf(a, v.y, acc.y);
        acc.z = fmaf(a, v.z, acc.z);
        acc.w = fmaf(a, v.w, acc.w);
    }
    const float inv = 1.f / (den + 1e-16f);
    float4 b = ((const float4*)b1)[t];
    acc.x = acc.x * inv + b.x;
    acc.y = acc.y * inv + b.y;
    acc.z = acc.z * inv + b.z;
    acc.w = acc.w * inv + b.w;
    acc.x = acc.x > 0.f ? acc.x : expm1f(acc.x);
    acc.y = acc.y > 0.f ? acc.y : expm1f(acc.y);
    acc.z = acc.z > 0.f ? acc.z : expm1f(acc.z);
    acc.w = acc.w > 0.f ? acc.w : expm1f(acc.w);
    *(float4*)(g_out1 + (size_t)d * D1 + t * 4) = acc;
}

// ---------------- GAT2 scalars ----------------
__global__ void scores2_kernel(const float* __restrict__ att_src2,
                               const float* __restrict__ att_dst2) {
    const int n = blockIdx.x;
    const int lane = threadIdx.x;
    const float* hr = g_h2pre + (size_t)n * OUTD;
    float sa = 0.f, sd = 0.f;
    for (int i = lane; i < OUTD; i += 32) {
        float v = hr[i];
        sa += v * att_src2[i];
        sd += v * att_dst2[i];
    }
#pragma unroll
    for (int o = 16; o > 0; o >>= 1) {
        sa += __shfl_xor_sync(0xffffffffu, sa, o);
        sd += __shfl_xor_sync(0xffffffffu, sd, o);
    }
    if (lane == 0) { g_as2[n] = sa; g_ad2[n] = sd; }
}

// ---------------- GAT2 aggregation: one warp per dst node ----------------
__global__ __launch_bounds__(256)
void agg2_kernel(const float* __restrict__ b2) {
    const int wid = (blockIdx.x * blockDim.x + threadIdx.x) >> 5;
    if (wid >= NN) return;
    const int d = wid;
    const int lane = threadIdx.x & 31;
    const int beg = __ldg(&g_off[d]);
    const int end = __ldg(&g_off[d + 1]);
    const float ad = g_ad2[d];

    float a0 = 0.f, a1 = 0.f, den = 0.f;
    for (int i = beg; i < end; i++) {
        const int s = __ldg(&g_csrc[i]);
        const float a = expf(lrelu(__ldg(&g_as2[s]) + ad));
        den += a;
        a0 = fmaf(a, __ldg(g_h2pre + (size_t)s * OUTD + lane), a0);
        a1 = fmaf(a, __ldg(g_h2pre + (size_t)s * OUTD + 32 + lane), a1);
    }
    const float inv = 1.f / (den + 1e-16f);
    g_out2[(size_t)d * OUTD + lane]      = a0 * inv + b2[lane];
    g_out2[(size_t)d * OUTD + 32 + lane] = a1 * inv + b2[32 + lane];
}

// ---------------- intra-attention MLP score ----------------
__global__ void attn_score_kernel(const float* __restrict__ Wa,
                                  const float* __restrict__ ba,
                                  const float* __restrict__ wv,
                                  const float* __restrict__ bv) {
    const int n = blockIdx.x;
    const int j = threadIdx.x;          // 64 threads
    __shared__ float hrow[OUTD];
    __shared__ float sh[OUTD];
    hrow[j] = g_out2[(size_t)n * OUTD + j];
    __syncthreads();
    float acc = 0.f;
#pragma unroll
    for (int k = 0; k < OUTD; k++) acc += hrow[k] * Wa[k * OUTD + j];
    sh[j] = tanhf(acc + ba[j]) * wv[j];
    __syncthreads();
    if (j < 32) sh[j] += sh[j + 32];
    __syncthreads();
    if (j == 0) {
        float s = 0.f;
#pragma unroll
        for (int k = 0; k < 32; k++) s += sh[k];
        g_scores[n] = s + bv[0];
    }
}

// ---------------- global softmax reduction + class_attn normalize ----------------
__global__ void global_reduce_kernel(const float* __restrict__ class_attn) {
    __shared__ float sm[1024];
    const int t = threadIdx.x;
    float m = -CUDART_INF_F;
    for (int i = t; i < NN; i += 1024) m = fmaxf(m, g_scores[i]);
    sm[t] = m; __syncthreads();
    for (int s = 512; s > 0; s >>= 1) { if (t < s) sm[t] = fmaxf(sm[t], sm[t + s]); __syncthreads(); }
    const float gmax = sm[0];
    __syncthreads();
    float ssum = 0.f;
    for (int i = t; i < NN; i += 1024) ssum += expf(g_scores[i] - gmax);
    sm[t] = ssum; __syncthreads();
    for (int s = 512; s > 0; s >>= 1) { if (t < s) sm[t] += sm[t + s]; __syncthreads(); }
    if (t == 0) { g_red2[0] = gmax; g_red2[1] = sm[0]; }

    if (t < NC * 32) {
        int c = t >> 5, lane = t & 31;
        float sq = 0.f;
        for (int jj = lane; jj < OUTD; jj += 32) { float v = class_attn[c * OUTD + jj]; sq += v * v; }
#pragma unroll
        for (int o = 16; o > 0; o >>= 1) sq += __shfl_xor_sync(0xffffffffu, sq, o);
        float nrm = fmaxf(sqrtf(sq), 1e-12f);
        for (int jj = lane; jj < OUTD; jj += 32) g_cn[c * OUTD + jj] = class_attn[c * OUTD + jj] / nrm;
    }
}

// ---------------- final epilogue ----------------
__global__ void final_kernel(const float* __restrict__ Wc,
                             const float* __restrict__ bc,
                             float* __restrict__ out) {
    const int n = blockIdx.x;
    const int j = threadIdx.x;  // 64 threads
    __shared__ float sxw[OUTD];
    __shared__ float ssq[OUTD];
    const float attw = expf(g_scores[n] - g_red2[0]) / g_red2[1];
    const float xw = g_out2[(size_t)n * OUTD + j] * attw;
    sxw[j] = xw;
    ssq[j] = xw * xw;
    out[(size_t)NN * NC + (size_t)n * OUTD + j] = xw;
    __syncthreads();
    if (j < 32) ssq[j] += ssq[j + 32];
    __syncthreads();
    if (j == 0) {
        float s = 0.f;
#pragma unroll
        for (int k = 0; k < 32; k++) s += ssq[k];
        ssq[0] = fmaxf(sqrtf(s), 1e-12f);
    }
    __syncthreads();
    const float inv = 1.f / ssq[0];
    if (j < NC) {
        float accI = 0.f, accO = bc[j];
#pragma unroll
        for (int k = 0; k < OUTD; k++) {
            accI += sxw[k] * inv * g_cn[j * OUTD + k];
            accO += sxw[k] * Wc[k * NC + j];
        }
        out[(size_t)n * NC + j] = accO;
        out[(size_t)NN * (NC + OUTD) + (size_t)n * NC + j] = accI;
    }
}

// ---------------- launch ----------------
extern "C" void kernel_launch(void* const* d_in, const int* in_sizes, int n_in,
                              void* d_out, int out_size) {
    const float* x        = (const float*)d_in[0];
    const int*   ei       = (const int*)  d_in[1];
    const float* W1       = (const float*)d_in[2];
    const float* att_src1 = (const float*)d_in[3];
    const float* att_dst1 = (const float*)d_in[4];
    const float* b1       = (const float*)d_in[5];
    const float* W2       = (const float*)d_in[6];
    const float* att_src2 = (const float*)d_in[7];
    const float* att_dst2 = (const float*)d_in[8];
    const float* b2       = (const float*)d_in[9];
    const float* Wa       = (const float*)d_in[10];
    const float* ba       = (const float*)d_in[11];
    const float* wv       = (const float*)d_in[12];
    const float* bv       = (const float*)d_in[13];
    const float* class_attn = (const float*)d_in[14];
    const float* Wc       = (const float*)d_in[15];
    const float* bc       = (const float*)d_in[16];
    float* out = (float*)d_out;

    float *h1pre_p, *out1_p, *h2pre_p;
    cudaGetSymbolAddress((void**)&h1pre_p, g_h1pre);
    cudaGetSymbolAddress((void**)&out1_p,  g_out1);
    cudaGetSymbolAddress((void**)&h2pre_p, g_h2pre);

    // CSR build (by destination)
    zero_deg_kernel<<<(NN + 255) / 256, 256>>>();
    hist_kernel<<<1480, 256>>>(ei);
    scan_kernel<<<1, 1024>>>();
    scatter_kernel<<<1480, 256>>>(ei);

    // GEMM1: [50000,512] @ [512,512]
    {
        dim3 grid(D1 / 128, (NN + 127) / 128);
        sgemm_kernel<128, 128, 16, 8, 8, IND, D1><<<grid, 256>>>(NN, x, W1, h1pre_p);
    }
    scores1_kernel<<<NN, 128>>>(att_src1, att_dst1);
    agg1_kernel<<<NN, 128>>>(b1);

    // GEMM2: [50000,512] @ [512,64]
    {
        dim3 grid(OUTD / 64, (NN + 127) / 128);
        sgemm_kernel<128, 64, 16, 8, 4, D1, OUTD><<<grid, 256>>>(NN, out1_p, W2, h2pre_p);
    }
    scores2_kernel<<<NN, 32>>>(att_src2, att_dst2);
    agg2_kernel<<<(NN * 32 + 255) / 256, 256>>>(b2);

    attn_score_kernel<<<NN, 64>>>(Wa, ba, wv, bv);
    global_reduce_kernel<<<1, 1024>>>(class_attn);
    final_kernel<<<NN, 64>>>(Wc, bc, out);
}

// round 6
// speedup vs baseline: 2.5158x; 1.2082x over previous
#include <cuda_runtime.h>
#include <math.h>
#include <math_constants.h>
#include <stdint.h>

// ---------------- problem constants ----------------
#define NN    50000
#define EE    800000
#define ENT   (EE + NN)          // edges incl. self loops
#define IND   512
#define HID   128
#define HEADS 4
#define D1    (HEADS * HID)      // 512
#define OUTD  64
#define NC    4

// ---------------- scratch (static device memory) ----------------
__device__ __align__(16) float g_h1pre[(size_t)NN * D1];
__device__ __align__(16) float g_out1 [(size_t)NN * D1];   // h1 (post act)
__device__ __align__(16) float g_h2pre[(size_t)NN * OUTD];
__device__ __align__(16) float g_out2 [(size_t)NN * OUTD]; // h2 (final)
__device__ float g_as1[NN * HEADS], g_ad1[NN * HEADS];
__device__ float g_as2[NN], g_ad2[NN];
__device__ float g_scores[NN];
__device__ float g_red2[2];
__device__ float g_cn[NC * OUTD];
// CSR by destination
__device__ int g_deg[NN];
__device__ int g_off[NN + 1];
__device__ int g_cur[NN];
__device__ int g_csrc[ENT];

__device__ __forceinline__ float lrelu(float v) { return v > 0.f ? v : 0.2f * v; }

// ---------------- CSR build ----------------
__global__ void zero_deg_kernel() {
    int i = blockIdx.x * blockDim.x + threadIdx.x;
    if (i < NN) g_deg[i] = 0;
}

__global__ void hist_kernel(const int* __restrict__ ei) {
    for (int e = blockIdx.x * blockDim.x + threadIdx.x; e < ENT;
         e += gridDim.x * blockDim.x) {
        int d = (e < EE) ? __ldg(ei + EE + e) : (e - EE);
        atomicAdd(&g_deg[d], 1);
    }
}

__global__ void scan_kernel() {
    __shared__ int sums[1024];
    const int t = threadIdx.x;
    const int per = (NN + 1023) / 1024;
    const int base = t * per;
    int lsum = 0;
    for (int i = 0; i < per; i++) {
        int idx = base + i;
        if (idx < NN) lsum += g_deg[idx];
    }
    sums[t] = lsum;
    __syncthreads();
    for (int o = 1; o < 1024; o <<= 1) {
        int y = (t >= o) ? sums[t - o] : 0;
        __syncthreads();
        sums[t] += y;
        __syncthreads();
    }
    int running = (t > 0) ? sums[t - 1] : 0;
    for (int i = 0; i < per; i++) {
        int idx = base + i;
        if (idx < NN) {
            g_off[idx] = running;
            g_cur[idx] = running;
            running += g_deg[idx];
        }
    }
    if (t == 0) g_off[NN] = ENT;
}

__global__ void scatter_kernel(const int* __restrict__ ei) {
    for (int e = blockIdx.x * blockDim.x + threadIdx.x; e < ENT;
         e += gridDim.x * blockDim.x) {
        int s = (e < EE) ? __ldg(ei + e) : (e - EE);
        int d = (e < EE) ? __ldg(ei + EE + e) : (e - EE);
        int pos = atomicAdd(&g_cur[d], 1);
        g_csrc[pos] = s;
    }
}

// ---------------- TF32 helpers ----------------
__device__ __forceinline__ void split_tf32(float x, uint32_t& hi, uint32_t& lo) {
    uint32_t h;
    asm("cvt.rna.tf32.f32 %0, %1;" : "=r"(h) : "f"(x));
    float l = x - __uint_as_float(h);
    uint32_t lr;
    asm("cvt.rna.tf32.f32 %0, %1;" : "=r"(lr) : "f"(l));
    hi = h; lo = lr;
}

__device__ __forceinline__ void mma_tf32(float* c, const uint32_t* a, const uint32_t* b) {
    asm volatile(
        "mma.sync.aligned.m16n8k8.row.col.f32.tf32.tf32.f32 "
        "{%0,%1,%2,%3}, {%4,%5,%6,%7}, {%8,%9}, {%0,%1,%2,%3};"
        : "+f"(c[0]), "+f"(c[1]), "+f"(c[2]), "+f"(c[3])
        : "r"(a[0]), "r"(a[1]), "r"(a[2]), "r"(a[3]), "r"(b[0]), "r"(b[1]));
}

// ---------------- 3xTF32 GEMM1: C[M,512] = A[M,512] @ B[512,512] ----------------
// block 128x128x32, 256 threads (8 warps as 2x4), warp tile 64x32, mma m16n8k8.
// smem swizzle: As elem off = m*32 + (k ^ (4*(m&7)))
//               Bs elem off = n*32 + (k ^ (4*(n&7)) ^ (n>>3))   [Bs holds B^T]
__global__ __launch_bounds__(256, 1)
void tf32_gemm1_kernel(int M, const float* __restrict__ A,
                       const float* __restrict__ B, float* __restrict__ C) {
    constexpr int K = 512, N = 512, BK = 32;
    __shared__ float As[128 * 32];
    __shared__ float Bs[128 * 32];

    const int tid  = threadIdx.x;
    const int wid  = tid >> 5;
    const int lane = tid & 31;
    const int warpM = wid >> 2;          // 0..1
    const int warpN = wid & 3;           // 0..3
    const int g = lane >> 2;             // 0..7
    const int c = lane & 3;              // 0..3
    const int rowBase = blockIdx.y * 128;
    const int colBase = blockIdx.x * 128;

    // global-load mappings
    const int a_m  = tid >> 3;           // +32 per iter (4 iters -> 128 rows)
    const int a_k4 = tid & 7;            // float4 col
    const int b_r  = tid >> 5;           // k row, +8 per iter (4 iters -> 32 rows)
    const int b_c4 = tid & 31;           // float4 col in N

    float4 pa[4], pb[4];

    auto loadG = [&](int k0) {
#pragma unroll
        for (int i = 0; i < 4; i++) {
            int gr = rowBase + a_m + i * 32;
            pa[i] = (gr < M) ? *(const float4*)(A + (size_t)gr * K + k0 + a_k4 * 4)
                             : make_float4(0.f, 0.f, 0.f, 0.f);
        }
#pragma unroll
        for (int i = 0; i < 4; i++) {
            int kr = k0 + b_r + i * 8;
            pb[i] = *(const float4*)(B + (size_t)kr * N + colBase + b_c4 * 4);
        }
    };
    auto storeS = [&]() {
#pragma unroll
        for (int i = 0; i < 4; i++) {
            int m = a_m + i * 32;
            *(float4*)&As[m * 32 + ((a_k4 * 4) ^ (4 * (m & 7)))] = pa[i];
        }
#pragma unroll
        for (int i = 0; i < 4; i++) {
            int kr = b_r + i * 8;
            float v[4] = {pb[i].x, pb[i].y, pb[i].z, pb[i].w};
#pragma unroll
            for (int j = 0; j < 4; j++) {
                int n = b_c4 * 4 + j;
                Bs[n * 32 + (kr ^ (4 * (n & 7)) ^ (n >> 3))] = v[j];
            }
        }
    };

    float acc[4][4][4];
#pragma unroll
    for (int mt = 0; mt < 4; mt++)
#pragma unroll
        for (int nt = 0; nt < 4; nt++)
#pragma unroll
            for (int r = 0; r < 4; r++) acc[mt][nt][r] = 0.f;

    auto compute = [&]() {
#pragma unroll
        for (int k8 = 0; k8 < 4; k8++) {
            const int kk = k8 * 8;
            uint32_t ahi[4][4], alo[4][4], bhi[4][2], blo[4][2];
#pragma unroll
            for (int mt = 0; mt < 4; mt++) {
                const int m0 = warpM * 64 + mt * 16 + g;
#pragma unroll
                for (int e = 0; e < 4; e++) {
                    const int m = m0 + (e & 1) * 8;
                    const int k = kk + c + (e >> 1) * 4;
                    float v = As[m * 32 + (k ^ (4 * (m & 7)))];
                    split_tf32(v, ahi[mt][e], alo[mt][e]);
                }
            }
#pragma unroll
            for (int nt = 0; nt < 4; nt++) {
                const int n = warpN * 32 + nt * 8 + g;
                const int sw = (4 * (n & 7)) ^ (n >> 3);
#pragma unroll
                for (int e = 0; e < 2; e++) {
                    const int k = kk + c + e * 4;
                    float v = Bs[n * 32 + (k ^ sw)];
                    split_tf32(v, bhi[nt][e], blo[nt][e]);
                }
            }
#pragma unroll
            for (int mt = 0; mt < 4; mt++)
#pragma unroll
                for (int nt = 0; nt < 4; nt++) {
                    mma_tf32(acc[mt][nt], alo[mt], bhi[nt]);
                    mma_tf32(acc[mt][nt], ahi[mt], blo[nt]);
                    mma_tf32(acc[mt][nt], ahi[mt], bhi[nt]);
                }
        }
    };

    loadG(0);
    storeS();
    __syncthreads();
    for (int kt = 0; kt < K / BK; kt++) {
        if (kt < K / BK - 1) loadG((kt + 1) * BK);
        compute();
        __syncthreads();
        if (kt < K / BK - 1) {
            storeS();
            __syncthreads();
        }
    }

    // epilogue: float2 stores, row-guarded
#pragma unroll
    for (int mt = 0; mt < 4; mt++) {
        const int r0 = rowBase + warpM * 64 + mt * 16 + g;
#pragma unroll
        for (int nt = 0; nt < 4; nt++) {
            const int col = colBase + warpN * 32 + nt * 8 + c * 2;
            if (r0 < M)
                *(float2*)(C + (size_t)r0 * N + col) =
                    make_float2(acc[mt][nt][0], acc[mt][nt][1]);
            if (r0 + 8 < M)
                *(float2*)(C + (size_t)(r0 + 8) * N + col) =
                    make_float2(acc[mt][nt][2], acc[mt][nt][3]);
        }
    }
}

// ---------------- fp32 SGEMM (kept for GEMM2): C = A@B ----------------
template<int BM, int BN, int BK, int TM, int TN, int K, int N>
__global__ __launch_bounds__((BM / TM) * (BN / TN))
void sgemm_kernel(int M, const float* __restrict__ A,
                  const float* __restrict__ B, float* __restrict__ C) {
    constexpr int NT = (BM / TM) * (BN / TN);
    __shared__ float As[2][BK][BM];
    __shared__ float Bs[2][BK][BN];

    const int tid = threadIdx.x;
    const int tx = tid % (BN / TN);
    const int ty = tid / (BN / TN);
    const int rowBase = blockIdx.y * BM;
    const int colBase = blockIdx.x * BN;

    constexpr int A_K4 = BK / 4;
    constexpr int A_RS = NT / A_K4;
    constexpr int A_IT = BM / A_RS;
    const int a_row = tid / A_K4;
    const int a_col = (tid % A_K4) * 4;
    constexpr int B_N4 = BN / 4;
    constexpr int B_RS = NT / B_N4;
    constexpr int B_IT = BK / B_RS;
    const int b_row = tid / B_N4;
    const int b_col = (tid % B_N4) * 4;

    float4 aReg[A_IT], bReg[B_IT];

    auto loadG = [&](int k0) {
#pragma unroll
        for (int i = 0; i < A_IT; i++) {
            int gr = rowBase + a_row + i * A_RS;
            aReg[i] = (gr < M) ? *(const float4*)(A + (size_t)gr * K + k0 + a_col)
                               : make_float4(0.f, 0.f, 0.f, 0.f);
        }
#pragma unroll
        for (int i = 0; i < B_IT; i++)
            bReg[i] = *(const float4*)(B + (size_t)(k0 + b_row + i * B_RS) * N + colBase + b_col);
    };
    auto storeS = [&](int buf) {
#pragma unroll
        for (int i = 0; i < A_IT; i++) {
            int r = a_row + i * A_RS;
            As[buf][a_col + 0][r] = aReg[i].x;
            As[buf][a_col + 1][r] = aReg[i].y;
            As[buf][a_col + 2][r] = aReg[i].z;
            As[buf][a_col + 3][r] = aReg[i].w;
        }
#pragma unroll
        for (int i = 0; i < B_IT; i++)
            *(float4*)&Bs[buf][b_row + i * B_RS][b_col] = bReg[i];
    };

    float acc[TM][TN];
#pragma unroll
    for (int i = 0; i < TM; i++)
#pragma unroll
        for (int j = 0; j < TN; j++) acc[i][j] = 0.f;

    auto compute = [&](int buf) {
#pragma unroll
        for (int k = 0; k < BK; k++) {
            float ra[TM], rb[TN];
#pragma unroll
            for (int i = 0; i < TM; i++) ra[i] = As[buf][k][ty * TM + i];
#pragma unroll
            for (int j = 0; j < TN; j++) rb[j] = Bs[buf][k][tx * TN + j];
#pragma unroll
            for (int i = 0; i < TM; i++)
#pragma unroll
                for (int j = 0; j < TN; j++) acc[i][j] = fmaf(ra[i], rb[j], acc[i][j]);
        }
    };

    loadG(0);
    storeS(0);
    __syncthreads();
    int buf = 0;
    for (int k0 = BK; k0 < K; k0 += BK) {
        loadG(k0);
        compute(buf);
        storeS(buf ^ 1);
        __syncthreads();
        buf ^= 1;
    }
    compute(buf);

#pragma unroll
    for (int i = 0; i < TM; i++) {
        int gr = rowBase + ty * TM + i;
        if (gr >= M) continue;
#pragma unroll
        for (int j = 0; j < TN; j += 4) {
            float4 v = make_float4(acc[i][j], acc[i][j + 1], acc[i][j + 2], acc[i][j + 3]);
            *(float4*)(C + (size_t)gr * N + colBase + tx * TN + j) = v;
        }
    }
}

// ---------------- GAT1: per-node/head attention scalars ----------------
__global__ void scores1_kernel(const float* __restrict__ att_src1,
                               const float* __restrict__ att_dst1) {
    const int n = blockIdx.x;
    const int h = threadIdx.x >> 5;
    const int lane = threadIdx.x & 31;
    const float4* hr = (const float4*)(g_h1pre + (size_t)n * D1 + h * HID);
    const float4* as = (const float4*)(att_src1 + h * HID);
    const float4* ad = (const float4*)(att_dst1 + h * HID);
    float4 v = hr[lane];
    float4 a = as[lane];
    float4 d = ad[lane];
    float sa = v.x * a.x + v.y * a.y + v.z * a.z + v.w * a.w;
    float sd = v.x * d.x + v.y * d.y + v.z * d.z + v.w * d.w;
#pragma unroll
    for (int o = 16; o > 0; o >>= 1) {
        sa += __shfl_xor_sync(0xffffffffu, sa, o);
        sd += __shfl_xor_sync(0xffffffffu, sd, o);
    }
    if (lane == 0) { g_as1[n * HEADS + h] = sa; g_ad1[n * HEADS + h] = sd; }
}

// ---------------- GAT1 aggregation: one block (128 thr) per dst node ----------------
__global__ __launch_bounds__(128)
void agg1_kernel(const float* __restrict__ b1) {
    const int d = blockIdx.x;
    const int t = threadIdx.x;
    const int h = t >> 5;
    const int beg = __ldg(&g_off[d]);
    const int end = __ldg(&g_off[d + 1]);
    const float ad = g_ad1[d * HEADS + h];

    float4 acc = make_float4(0.f, 0.f, 0.f, 0.f);
    float den = 0.f;
    for (int i = beg; i < end; i++) {
        const int s = __ldg(&g_csrc[i]);
        const float a = expf(lrelu(__ldg(&g_as1[s * HEADS + h]) + ad));
        den += a;
        float4 v = *(const float4*)(g_h1pre + (size_t)s * D1 + t * 4);
        acc.x = fmaf(a, v.x, acc.x);
        acc.y = fmaf(a, v.y, acc.y);
        acc.z = fmaf(a, v.z, acc.z);
        acc.w = fmaf(a, v.w, acc.w);
    }
    const float inv = 1.f / (den + 1e-16f);
    float4 b = ((const float4*)b1)[t];
    acc.x = acc.x * inv + b.x;
    acc.y = acc.y * inv + b.y;
    acc.z = acc.z * inv + b.z;
    acc.w = acc.w * inv + b.w;
    acc.x = acc.x > 0.f ? acc.x : expm1f(acc.x);
    acc.y = acc.y > 0.f ? acc.y : expm1f(acc.y);
    acc.z = acc.z > 0.f ? acc.z : expm1f(acc.z);
    acc.w = acc.w > 0.f ? acc.w : expm1f(acc.w);
    *(float4*)(g_out1 + (size_t)d * D1 + t * 4) = acc;
}

// ---------------- GAT2 scalars ----------------
__global__ void scores2_kernel(const float* __restrict__ att_src2,
                               const float* __restrict__ att_dst2) {
    const int n = blockIdx.x;
    const int lane = threadIdx.x;
    const float* hr = g_h2pre + (size_t)n * OUTD;
    float sa = 0.f, sd = 0.f;
    for (int i = lane; i < OUTD; i += 32) {
        float v = hr[i];
        sa += v * att_src2[i];
        sd += v * att_dst2[i];
    }
#pragma unroll
    for (int o = 16; o > 0; o >>= 1) {
        sa += __shfl_xor_sync(0xffffffffu, sa, o);
        sd += __shfl_xor_sync(0xffffffffu, sd, o);
    }
    if (lane == 0) { g_as2[n] = sa; g_ad2[n] = sd; }
}

// ---------------- GAT2 aggregation: one warp per dst node ----------------
__global__ __launch_bounds__(256)
void agg2_kernel(const float* __restrict__ b2) {
    const int wid = (blockIdx.x * blockDim.x + threadIdx.x) >> 5;
    if (wid >= NN) return;
    const int d = wid;
    const int lane = threadIdx.x & 31;
    const int beg = __ldg(&g_off[d]);
    const int end = __ldg(&g_off[d + 1]);
    const float ad = g_ad2[d];

    float a0 = 0.f, a1 = 0.f, den = 0.f;
    for (int i = beg; i < end; i++) {
        const int s = __ldg(&g_csrc[i]);
        const float a = expf(lrelu(__ldg(&g_as2[s]) + ad));
        den += a;
        a0 = fmaf(a, __ldg(g_h2pre + (size_t)s * OUTD + lane), a0);
        a1 = fmaf(a, __ldg(g_h2pre + (size_t)s * OUTD + 32 + lane), a1);
    }
    const float inv = 1.f / (den + 1e-16f);
    g_out2[(size_t)d * OUTD + lane]      = a0 * inv + b2[lane];
    g_out2[(size_t)d * OUTD + 32 + lane] = a1 * inv + b2[32 + lane];
}

// ---------------- intra-attention MLP score ----------------
__global__ void attn_score_kernel(const float* __restrict__ Wa,
                                  const float* __restrict__ ba,
                                  const float* __restrict__ wv,
                                  const float* __restrict__ bv) {
    const int n = blockIdx.x;
    const int j = threadIdx.x;          // 64 threads
    __shared__ float hrow[OUTD];
    __shared__ float sh[OUTD];
    hrow[j] = g_out2[(size_t)n * OUTD + j];
    __syncthreads();
    float acc = 0.f;
#pragma unroll
    for (int k = 0; k < OUTD; k++) acc += hrow[k] * Wa[k * OUTD + j];
    sh[j] = tanhf(acc + ba[j]) * wv[j];
    __syncthreads();
    if (j < 32) sh[j] += sh[j + 32];
    __syncthreads();
    if (j == 0) {
        float s = 0.f;
#pragma unroll
        for (int k = 0; k < 32; k++) s += sh[k];
        g_scores[n] = s + bv[0];
    }
}

// ---------------- global softmax reduction + class_attn normalize ----------------
__global__ void global_reduce_kernel(const float* __restrict__ class_attn) {
    __shared__ float sm[1024];
    const int t = threadIdx.x;
    float m = -CUDART_INF_F;
    for (int i = t; i < NN; i += 1024) m = fmaxf(m, g_scores[i]);
    sm[t] = m; __syncthreads();
    for (int s = 512; s > 0; s >>= 1) { if (t < s) sm[t] = fmaxf(sm[t], sm[t + s]); __syncthreads(); }
    const float gmax = sm[0];
    __syncthreads();
    float ssum = 0.f;
    for (int i = t; i < NN; i += 1024) ssum += expf(g_scores[i] - gmax);
    sm[t] = ssum; __syncthreads();
    for (int s = 512; s > 0; s >>= 1) { if (t < s) sm[t] += sm[t + s]; __syncthreads(); }
    if (t == 0) { g_red2[0] = gmax; g_red2[1] = sm[0]; }

    if (t < NC * 32) {
        int c = t >> 5, lane = t & 31;
        float sq = 0.f;
        for (int jj = lane; jj < OUTD; jj += 32) { float v = class_attn[c * OUTD + jj]; sq += v * v; }
#pragma unroll
        for (int o = 16; o > 0; o >>= 1) sq += __shfl_xor_sync(0xffffffffu, sq, o);
        float nrm = fmaxf(sqrtf(sq), 1e-12f);
        for (int jj = lane; jj < OUTD; jj += 32) g_cn[c * OUTD + jj] = class_attn[c * OUTD + jj] / nrm;
    }
}

// ---------------- final epilogue ----------------
__global__ void final_kernel(const float* __restrict__ Wc,
                             const float* __restrict__ bc,
                             float* __restrict__ out) {
    const int n = blockIdx.x;
    const int j = threadIdx.x;  // 64 threads
    __shared__ float sxw[OUTD];
    __shared__ float ssq[OUTD];
    const float attw = expf(g_scores[n] - g_red2[0]) / g_red2[1];
    const float xw = g_out2[(size_t)n * OUTD + j] * attw;
    sxw[j] = xw;
    ssq[j] = xw * xw;
    out[(size_t)NN * NC + (size_t)n * OUTD + j] = xw;
    __syncthreads();
    if (j < 32) ssq[j] += ssq[j + 32];
    __syncthreads();
    if (j == 0) {
        float s = 0.f;
#pragma unroll
        for (int k = 0; k < 32; k++) s += ssq[k];
        ssq[0] = fmaxf(sqrtf(s), 1e-12f);
    }
    __syncthreads();
    const float inv = 1.f / ssq[0];
    if (j < NC) {
        float accI = 0.f, accO = bc[j];
#pragma unroll
        for (int k = 0; k < OUTD; k++) {
            accI += sxw[k] * inv * g_cn[j * OUTD + k];
            accO += sxw[k] * Wc[k * NC + j];
        }
        out[(size_t)n * NC + j] = accO;
        out[(size_t)NN * (NC + OUTD) + (size_t)n * NC + j] = accI;
    }
}

// ---------------- launch ----------------
extern "C" void kernel_launch(void* const* d_in, const int* in_sizes, int n_in,
                              void* d_out, int out_size) {
    const float* x        = (const float*)d_in[0];
    const int*   ei       = (const int*)  d_in[1];
    const float* W1       = (const float*)d_in[2];
    const float* att_src1 = (const float*)d_in[3];
    const float* att_dst1 = (const float*)d_in[4];
    const float* b1       = (const float*)d_in[5];
    const float* W2       = (const float*)d_in[6];
    const float* att_src2 = (const float*)d_in[7];
    const float* att_dst2 = (const float*)d_in[8];
    const float* b2       = (const float*)d_in[9];
    const float* Wa       = (const float*)d_in[10];
    const float* ba       = (const float*)d_in[11];
    const float* wv       = (const float*)d_in[12];
    const float* bv       = (const float*)d_in[13];
    const float* class_attn = (const float*)d_in[14];
    const float* Wc       = (const float*)d_in[15];
    const float* bc       = (const float*)d_in[16];
    float* out = (float*)d_out;

    float *h1pre_p, *out1_p, *h2pre_p;
    cudaGetSymbolAddress((void**)&h1pre_p, g_h1pre);
    cudaGetSymbolAddress((void**)&out1_p,  g_out1);
    cudaGetSymbolAddress((void**)&h2pre_p, g_h2pre);

    // CSR build (by destination)
    zero_deg_kernel<<<(NN + 255) / 256, 256>>>();
    hist_kernel<<<1480, 256>>>(ei);
    scan_kernel<<<1, 1024>>>();
    scatter_kernel<<<1480, 256>>>(ei);

    // GEMM1: [50000,512] @ [512,512] via 3xTF32 tensor cores
    {
        dim3 grid(D1 / 128, (NN + 127) / 128);
        tf32_gemm1_kernel<<<grid, 256>>>(NN, x, W1, h1pre_p);
    }
    scores1_kernel<<<NN, 128>>>(att_src1, att_dst1);
    agg1_kernel<<<NN, 128>>>(b1);

    // GEMM2: [50000,512] @ [512,64] (fp32)
    {
        dim3 grid(OUTD / 64, (NN + 127) / 128);
        sgemm_kernel<128, 64, 16, 8, 4, D1, OUTD><<<grid, 256>>>(NN, out1_p, W2, h2pre_p);
    }
    scores2_kernel<<<NN, 32>>>(att_src2, att_dst2);
    agg2_kernel<<<(NN * 32 + 255) / 256, 256>>>(b2);

    attn_score_kernel<<<NN, 64>>>(Wa, ba, wv, bv);
    global_reduce_kernel<<<1, 1024>>>(class_attn);
    final_kernel<<<NN, 64>>>(Wc, bc, out);
}